// round 2
// baseline (speedup 1.0000x reference)
#include <cuda_runtime.h>
#include <math.h>

#define BB   1024
#define VV   8
#define ND   32
#define NPR  16
#define NM   24
#define DD   256
#define BV   (BB*VV)
#define VOCD 2000
#define VOCP 1500
#define VOCM 131
#define PAD  260
#define EPSV 1e-8f

// ---------------- static device scratch (no cudaMalloc anywhere) ----------------
__device__ __align__(16) float g_HD[VOCD*DD];
__device__ __align__(16) float g_HP[VOCP*DD];
__device__ __align__(16) float g_HM[VOCM*DD];
__device__ __align__(16) float g_homo0[BV*DD];
__device__ __align__(16) float g_homo1[BV*DD];
__device__ __align__(16) float g_homo2[BV*DD];
__device__ __align__(16) float g_u0[BV*DD];
__device__ __align__(16) float g_u1[BV*DD];
__device__ __align__(16) float g_u2[BV*DD];
__device__ __align__(16) float g_u3[BV*DD];
__device__ __align__(16) float g_seq0[BV*DD];
__device__ __align__(16) float g_seq1[BV*DD];
__device__ __align__(16) float g_seq2[BV*DD];
__device__ __align__(16) float g_gi[3ull*BV*768];
__device__ __align__(16) float g_wihT[3*256*768];
__device__ __align__(16) float g_whhT[3*256*768];
__device__ __align__(16) float g_h[3*BB*DD];
__device__ __align__(16) float g_Wq2T[768*VOCM];
__device__ __align__(16) float g_p[BB*VOCM];
__device__ float g_bpart[BB];

// ---------------- init: zero GRU hidden state ----------------
__global__ void k_init()
{
    int i = blockIdx.x*blockDim.x + threadIdx.x;
    if (i < 3*BB*DD) g_h[i] = 0.f;
}

// ---------------- K0a: H = E @ W_homo[set] ----------------
__global__ void __launch_bounds__(256) k0_ew(const float* __restrict__ Ed,
                                             const float* __restrict__ Ep,
                                             const float* __restrict__ Em,
                                             const float* __restrict__ Wh)
{
    __shared__ __align__(16) float se[32*256];
    int set = blockIdx.y;
    int rows = (set==0) ? VOCD : (set==1) ? VOCP : VOCM;
    int r0 = blockIdx.x * 32;
    if (r0 >= rows) return;
    const float* E = (set==0) ? Ed : (set==1) ? Ep : Em;
    float* O       = (set==0) ? g_HD : (set==1) ? g_HP : g_HM;
    const float* W = Wh + (size_t)set*DD*DD;
    int tid = threadIdx.x;

    for (int i = tid; i < 32*64; i += 256) {
        int r = i >> 6, c = i & 63;
        float4 v = (r0 + r < rows) ? __ldg((const float4*)(E + (size_t)(r0+r)*DD) + c)
                                   : make_float4(0.f,0.f,0.f,0.f);
        ((float4*)se)[r*64 + c] = v;
    }
    __syncthreads();

    float acc[32];
    #pragma unroll
    for (int r = 0; r < 32; r++) acc[r] = 0.f;
    for (int k = 0; k < DD; k += 4) {
        float w0 = __ldg(W + (size_t)k*DD + tid);
        float w1 = __ldg(W + (size_t)(k+1)*DD + tid);
        float w2 = __ldg(W + (size_t)(k+2)*DD + tid);
        float w3 = __ldg(W + (size_t)(k+3)*DD + tid);
        #pragma unroll
        for (int r = 0; r < 32; r++) {
            float4 x = *(const float4*)(se + r*256 + k);
            acc[r] = fmaf(x.x,w0,fmaf(x.y,w1,fmaf(x.z,w2,fmaf(x.w,w3,acc[r]))));
        }
    }
    for (int r = 0; r < 32; r++)
        if (r0 + r < rows) O[(size_t)(r0+r)*DD + tid] = acc[r];
}

// ---------------- K0b: transposes + folded Wq ----------------
__global__ void k0_tr(const float* __restrict__ wih,
                      const float* __restrict__ whh,
                      const float* __restrict__ Wq)
{
    const int N1 = 3*768*256;
    const int TOT = 2*N1 + 768*VOCM;
    for (int i = blockIdx.x*blockDim.x + threadIdx.x; i < TOT; i += gridDim.x*blockDim.x) {
        if (i < N1) {
            int g = i/(768*256); int rem = i - g*768*256;
            int r = rem/256; int k = rem - r*256;
            g_wihT[g*768*256 + k*768 + r] = wih[i];
        } else if (i < 2*N1) {
            int j = i - N1;
            int g = j/(768*256); int rem = j - g*768*256;
            int r = rem/256; int k = rem - r*256;
            g_whhT[g*768*256 + k*768 + r] = whh[j];
        } else {
            int o = i - 2*N1;
            int k = o / VOCM, j = o - k*VOCM;
            g_Wq2T[o] = Wq[(size_t)j*1536 + k] + Wq[(size_t)j*1536 + 768 + k];
        }
    }
}

// ---------------- attention helper ----------------
// returns (colsum(softmax(masked h h^T / 16)) . h)[tid]
template<int N>
__device__ __forceinline__ float attn_out(const float* __restrict__ adj,
                                          const float* sh, float* ss, float* scs, int tid)
{
    for (int p = tid; p < N*N; p += 256) {
        int n = p / N, m = p - n*N;
        const float4* ha = (const float4*)(sh + n*PAD);
        const float4* hb = (const float4*)(sh + m*PAD);
        float a0 = 0.f, a1 = 0.f;
        #pragma unroll 8
        for (int k = 0; k < 64; k += 2) {
            float4 a = ha[k],   b = hb[k];
            float4 c = ha[k+1], d = hb[k+1];
            a0 += a.x*b.x + a.y*b.y + a.z*b.z + a.w*b.w;
            a1 += c.x*d.x + c.y*d.y + c.z*d.z + c.w*d.w;
        }
        float sc = (a0 + a1) * 0.0625f;
        float av = __ldg(adj + p);
        ss[n*33 + m] = ((av > 0.5f) || (n == m)) ? sc : -1e9f;
    }
    __syncthreads();
    int lane = tid & 31;
    for (int n = tid >> 5; n < N; n += 8) {
        float val = (lane < N) ? ss[n*33 + lane] : -3.0e38f;
        float mx = val;
        #pragma unroll
        for (int o = 16; o > 0; o >>= 1) mx = fmaxf(mx, __shfl_xor_sync(0xffffffffu, mx, o));
        float e = (lane < N) ? __expf(val - mx) : 0.f;
        float s = e;
        #pragma unroll
        for (int o = 16; o > 0; o >>= 1) s += __shfl_xor_sync(0xffffffffu, s, o);
        if (lane < N) ss[n*33 + lane] = e / s;
    }
    __syncthreads();
    if (tid < N) {
        float c = 0.f;
        #pragma unroll
        for (int n = 0; n < N; n++) c += ss[n*33 + tid];
        scs[tid] = c;
    }
    __syncthreads();
    float o = 0.f;
    #pragma unroll
    for (int m = 0; m < N; m++) o = fmaf(scs[m], sh[m*PAD + tid], o);
    return o;
}

// ---------------- K1: per-(b,v) fused homo sums + hetero u vectors ----------------
__global__ void __launch_bounds__(256) k1_kernel(
    const int* __restrict__ idx_d, const int* __restrict__ idx_p, const int* __restrict__ idx_m,
    const float* __restrict__ adj_d, const float* __restrict__ adj_p, const float* __restrict__ adj_m,
    const float* __restrict__ wdm_g, const float* __restrict__ wpm_g,
    const float* __restrict__ E_d, const float* __restrict__ E_p, const float* __restrict__ E_m)
{
    __shared__ __align__(16) float sh[32*PAD];
    __shared__ float ss[32*33];
    __shared__ float sw[ND*NM];
    __shared__ float scdm[NM], scpm[NM], scmd[ND], scmp[NPR];
    __shared__ float srow[ND], scol[NM], scs[32];
    __shared__ int sidx[ND];

    int bid = blockIdx.x;
    int v = bid & 7;
    int tid = threadIdx.x;
    size_t off = (size_t)bid*DD + tid;

    float u_d = 0.f, u_p = 0.f, sm_out = 0.f;
    if (v > 0) {
        const float* wdm = wdm_g + (size_t)bid*ND*NM;
        for (int i = tid; i < ND*NM; i += 256) sw[i] = wdm[i];
        if (tid < NM) sidx[tid] = __ldg(idx_m + (size_t)(bid-1)*NM + tid);
        __syncthreads();
        for (int i = tid; i < NM*64; i += 256) {
            int r = i >> 6, c = i & 63;
            ((float4*)(sh + r*PAD))[c] = __ldg((const float4*)(g_HM + (size_t)sidx[r]*DD) + c);
        }
        if (tid < ND) { float s = 0.f; for (int m=0;m<NM;m++) s += sw[tid*NM+m]; srow[tid] = s + EPSV; }
        __syncthreads();
        if (tid < NM) {
            float c = 0.f, cs = 0.f;
            for (int n=0;n<ND;n++) { float w = sw[n*NM+tid]; c += w/srow[n]; cs += w; }
            scdm[tid] = c; scol[tid] = cs + EPSV;
        }
        __syncthreads();
        if (tid < ND) { float c = 0.f; for (int m=0;m<NM;m++) c += sw[tid*NM+m]/scol[m]; scmd[tid] = c; }
        __syncthreads();
        const float* wpm = wpm_g + (size_t)bid*NPR*NM;
        for (int i = tid; i < NPR*NM; i += 256) sw[i] = wpm[i];
        __syncthreads();
        if (tid < NPR) { float s = 0.f; for (int m=0;m<NM;m++) s += sw[tid*NM+m]; srow[tid] = s + EPSV; }
        __syncthreads();
        if (tid < NM) {
            float c = 0.f, cs = 0.f;
            for (int n=0;n<NPR;n++) { float w = sw[n*NM+tid]; c += w/srow[n]; cs += w; }
            scpm[tid] = c; scol[tid] = cs + EPSV;
        }
        __syncthreads();
        if (tid < NPR) { float c = 0.f; for (int m=0;m<NM;m++) c += sw[tid*NM+m]/scol[m]; scmp[tid] = c; }
        __syncthreads();
        #pragma unroll 4
        for (int m = 0; m < NM; m++) {
            float e = __ldg(E_m + (size_t)sidx[m]*DD + tid);
            u_d = fmaf(scdm[m], e, u_d);
            u_p = fmaf(scpm[m], e, u_p);
        }
        sm_out = attn_out<NM>(adj_m + (size_t)bid*NM*NM, sh, ss, scs, tid);
    }
    g_homo2[off] = sm_out; g_u0[off] = u_d; g_u1[off] = u_p;
    __syncthreads();

    // ---- diag ----
    if (tid < ND) sidx[tid] = __ldg(idx_d + (size_t)bid*ND + tid);
    __syncthreads();
    for (int i = tid; i < ND*64; i += 256) {
        int r = i >> 6, c = i & 63;
        ((float4*)(sh + r*PAD))[c] = __ldg((const float4*)(g_HD + (size_t)sidx[r]*DD) + c);
    }
    __syncthreads();
    float sd_out = attn_out<ND>(adj_d + (size_t)bid*ND*ND, sh, ss, scs, tid);
    float u_md = 0.f;
    if (v > 0) {
        #pragma unroll 4
        for (int n = 0; n < ND; n++)
            u_md = fmaf(scmd[n], __ldg(E_d + (size_t)sidx[n]*DD + tid), u_md);
    }
    g_homo0[off] = sd_out; g_u2[off] = u_md;
    __syncthreads();

    // ---- proc ----
    if (tid < NPR) sidx[tid] = __ldg(idx_p + (size_t)bid*NPR + tid);
    __syncthreads();
    for (int i = tid; i < NPR*64; i += 256) {
        int r = i >> 6, c = i & 63;
        ((float4*)(sh + r*PAD))[c] = __ldg((const float4*)(g_HP + (size_t)sidx[r]*DD) + c);
    }
    __syncthreads();
    float sp_out = attn_out<NPR>(adj_p + (size_t)bid*NPR*NPR, sh, ss, scs, tid);
    float u_mp = 0.f;
    if (v > 0) {
        #pragma unroll 4
        for (int n = 0; n < NPR; n++)
            u_mp = fmaf(scmp[n], __ldg(E_p + (size_t)sidx[n]*DD + tid), u_mp);
    }
    g_homo1[off] = sp_out; g_u3[off] = u_mp;
}

// ---------------- K2: seq = rho0*homo + rho1*(u @ Wh) ----------------
__global__ void __launch_bounds__(256) k2_seq(const float* __restrict__ Wh_d,
                                              const float* __restrict__ Wh_p,
                                              const float* __restrict__ Wh_md,
                                              const float* __restrict__ Wh_mp,
                                              const float* __restrict__ rho)
{
    __shared__ __align__(16) float su[32*256];
    int set = blockIdx.y;
    int r0 = blockIdx.x * 32;
    int tid = threadIdx.x;
    const float* U1 = (set==0) ? g_u0 : (set==1) ? g_u1 : g_u2;
    const float* W1 = (set==0) ? Wh_d : (set==1) ? Wh_p : Wh_md;

    float acc[32];
    #pragma unroll
    for (int r = 0; r < 32; r++) acc[r] = 0.f;
    for (int i = tid; i < 32*256; i += 256) su[i] = U1[(size_t)r0*256 + i];
    __syncthreads();
    for (int k = 0; k < 256; k += 4) {
        float w0 = __ldg(W1 + (size_t)k*256 + tid);
        float w1 = __ldg(W1 + (size_t)(k+1)*256 + tid);
        float w2 = __ldg(W1 + (size_t)(k+2)*256 + tid);
        float w3 = __ldg(W1 + (size_t)(k+3)*256 + tid);
        #pragma unroll
        for (int r = 0; r < 32; r++) {
            float4 x = *(const float4*)(su + r*256 + k);
            acc[r] = fmaf(x.x,w0,fmaf(x.y,w1,fmaf(x.z,w2,fmaf(x.w,w3,acc[r]))));
        }
    }
    if (set == 2) {
        __syncthreads();
        for (int i = tid; i < 32*256; i += 256) su[i] = g_u3[(size_t)r0*256 + i];
        __syncthreads();
        for (int k = 0; k < 256; k += 4) {
            float w0 = __ldg(Wh_mp + (size_t)k*256 + tid);
            float w1 = __ldg(Wh_mp + (size_t)(k+1)*256 + tid);
            float w2 = __ldg(Wh_mp + (size_t)(k+2)*256 + tid);
            float w3 = __ldg(Wh_mp + (size_t)(k+3)*256 + tid);
            #pragma unroll
            for (int r = 0; r < 32; r++) {
                float4 x = *(const float4*)(su + r*256 + k);
                acc[r] = fmaf(x.x,w0,fmaf(x.y,w1,fmaf(x.z,w2,fmaf(x.w,w3,acc[r]))));
            }
        }
    }
    float rh0 = __ldg(rho + set*2), rh1 = __ldg(rho + set*2 + 1);
    const float* H = (set==0) ? g_homo0 : (set==1) ? g_homo1 : g_homo2;
    float* S       = (set==0) ? g_seq0 : (set==1) ? g_seq1 : g_seq2;
    for (int r = 0; r < 32; r++) {
        size_t o = (size_t)(r0+r)*256 + tid;
        S[o] = rh0 * H[o] + rh1 * acc[r];
    }
}

// ---------------- K3: gi = seq @ wihT + bih ----------------
__global__ void __launch_bounds__(256) k3_gi(const float* __restrict__ bih)
{
    __shared__ __align__(16) float su[32*256];
    int g = blockIdx.z;
    int j = blockIdx.y*256 + threadIdx.x;
    int r0 = blockIdx.x * 32;
    int tid = threadIdx.x;
    const float* S = (g==0) ? g_seq0 : (g==1) ? g_seq1 : g_seq2;
    const float* W = g_wihT + (size_t)g*256*768;

    for (int i = tid; i < 32*256; i += 256) su[i] = S[(size_t)r0*256 + i];
    __syncthreads();
    float acc[32];
    #pragma unroll
    for (int r = 0; r < 32; r++) acc[r] = 0.f;
    for (int k = 0; k < 256; k += 4) {
        float w0 = __ldg(W + (size_t)k*768 + j);
        float w1 = __ldg(W + (size_t)(k+1)*768 + j);
        float w2 = __ldg(W + (size_t)(k+2)*768 + j);
        float w3 = __ldg(W + (size_t)(k+3)*768 + j);
        #pragma unroll
        for (int r = 0; r < 32; r++) {
            float4 x = *(const float4*)(su + r*256 + k);
            acc[r] = fmaf(x.x,w0,fmaf(x.y,w1,fmaf(x.z,w2,fmaf(x.w,w3,acc[r]))));
        }
    }
    float bias = __ldg(bih + g*768 + j);
    for (int r = 0; r < 32; r++)
        g_gi[((size_t)g*BV + r0 + r)*768 + j] = acc[r] + bias;
}

// ---------------- K4: one GRU time step ----------------
__global__ void __launch_bounds__(256) k4_step(const float* __restrict__ bhh, int t)
{
    __shared__ __align__(16) float sh16[16*256];
    int g = blockIdx.y;
    int r0 = blockIdx.x * 16;
    int tid = threadIdx.x;
    const float* W = g_whhT + (size_t)g*256*768;
    float* H = g_h + (size_t)g*BB*DD;

    for (int i = tid; i < 16*64; i += 256) {
        int r = i >> 6, c = i & 63;
        ((float4*)(sh16 + r*256))[c] = *(const float4*)(H + (size_t)(r0+r)*256 + c*4);
    }
    __syncthreads();
    float ar[16], az[16], an[16];
    #pragma unroll
    for (int r = 0; r < 16; r++) { ar[r]=0.f; az[r]=0.f; an[r]=0.f; }
    for (int k = 0; k < 256; k += 4) {
        float4 wr, wz, wn;
        wr.x=__ldg(W+(size_t)k*768+tid);           wr.y=__ldg(W+(size_t)(k+1)*768+tid);
        wr.z=__ldg(W+(size_t)(k+2)*768+tid);       wr.w=__ldg(W+(size_t)(k+3)*768+tid);
        wz.x=__ldg(W+(size_t)k*768+256+tid);       wz.y=__ldg(W+(size_t)(k+1)*768+256+tid);
        wz.z=__ldg(W+(size_t)(k+2)*768+256+tid);   wz.w=__ldg(W+(size_t)(k+3)*768+256+tid);
        wn.x=__ldg(W+(size_t)k*768+512+tid);       wn.y=__ldg(W+(size_t)(k+1)*768+512+tid);
        wn.z=__ldg(W+(size_t)(k+2)*768+512+tid);   wn.w=__ldg(W+(size_t)(k+3)*768+512+tid);
        #pragma unroll
        for (int r = 0; r < 16; r++) {
            float4 x = *(const float4*)(sh16 + r*256 + k);
            ar[r]=fmaf(x.x,wr.x,fmaf(x.y,wr.y,fmaf(x.z,wr.z,fmaf(x.w,wr.w,ar[r]))));
            az[r]=fmaf(x.x,wz.x,fmaf(x.y,wz.y,fmaf(x.z,wz.z,fmaf(x.w,wz.w,az[r]))));
            an[r]=fmaf(x.x,wn.x,fmaf(x.y,wn.y,fmaf(x.z,wn.z,fmaf(x.w,wn.w,an[r]))));
        }
    }
    float br = __ldg(bhh + g*768 + tid);
    float bz = __ldg(bhh + g*768 + 256 + tid);
    float bn = __ldg(bhh + g*768 + 512 + tid);
    for (int r = 0; r < 16; r++) {
        size_t gio = ((size_t)g*BV + (size_t)(r0+r)*VV + t)*768;
        float ir  = g_gi[gio + tid];
        float iz  = g_gi[gio + 256 + tid];
        float in_ = g_gi[gio + 512 + tid];
        float rr = 1.f/(1.f+__expf(-(ir + ar[r] + br)));
        float zz = 1.f/(1.f+__expf(-(iz + az[r] + bz)));
        float nn = tanhf(in_ + rr*(an[r] + bn));
        float hold = sh16[r*256 + tid];
        H[(size_t)(r0+r)*256 + tid] = (1.f - zz)*nn + zz*hold;
    }
}

// ---------------- K5: score + sigmoid ----------------
__global__ void __launch_bounds__(256) k5_score(const float* __restrict__ bq, float* __restrict__ out)
{
    __shared__ float shc[768];
    int b = blockIdx.x, tid = threadIdx.x;
    for (int i = tid; i < 768; i += 256) {
        int g = i >> 8, k = i & 255;
        float h = g_h[(size_t)g*BB*DD + (size_t)b*DD + k];
        shc[i] = fmaxf(h, 0.f);
    }
    __syncthreads();
    if (tid < VOCM) {
        float acc = 0.f;
        for (int k = 0; k < 768; k++) acc = fmaf(shc[k], __ldg(g_Wq2T + k*VOCM + tid), acc);
        float sc = acc + __ldg(bq + tid);
        out[(size_t)b*VOCM + tid] = sc;
        g_p[(size_t)b*VOCM + tid] = 1.f/(1.f+__expf(-sc));
    }
}

// ---------------- K6: per-b ddi partial ----------------
__global__ void __launch_bounds__(256) k6_ddi(const float* __restrict__ ddi)
{
    __shared__ float sp[VOCM];
    __shared__ float red[8];
    int b = blockIdx.x, tid = threadIdx.x;
    for (int i = tid; i < VOCM; i += 256) sp[i] = g_p[(size_t)b*VOCM + i];
    __syncthreads();
    float val = 0.f;
    if (tid < VOCM) {
        float q = 0.f;
        for (int i = 0; i < VOCM; i++) q = fmaf(sp[i], __ldg(ddi + (size_t)i*VOCM + tid), q);
        val = sp[tid]*q;
    }
    for (int o = 16; o > 0; o >>= 1) val += __shfl_xor_sync(0xffffffffu, val, o);
    if ((tid & 31) == 0) red[tid >> 5] = val;
    __syncthreads();
    if (tid == 0) {
        float s = 0.f;
        for (int w = 0; w < 8; w++) s += red[w];
        g_bpart[b] = s;
    }
}

// ---------------- K7: deterministic final reduction ----------------
__global__ void k7_final(float* __restrict__ out, int out_size)
{
    __shared__ float red[8];
    int tid = threadIdx.x;
    float s = 0.f;
    for (int i = tid; i < BB; i += 256) s += g_bpart[i];
    for (int o = 16; o > 0; o >>= 1) s += __shfl_xor_sync(0xffffffffu, s, o);
    if ((tid & 31) == 0) red[tid >> 5] = s;
    __syncthreads();
    if (tid == 0) {
        float t = 0.f;
        for (int w = 0; w < 8; w++) t += red[w];
        if (out_size > BB*VOCM) out[BB*VOCM] = 0.0005f * t;
    }
}

// ---------------- launch ----------------
extern "C" void kernel_launch(void* const* d_in, const int* in_sizes, int n_in,
                              void* d_out, int out_size)
{
    const int*   idx_d  = (const int*)d_in[0];
    const int*   idx_p  = (const int*)d_in[1];
    const int*   idx_m  = (const int*)d_in[2];
    const float* adj_d  = (const float*)d_in[3];
    const float* adj_p  = (const float*)d_in[4];
    const float* adj_m  = (const float*)d_in[5];
    const float* w_dm   = (const float*)d_in[6];
    const float* w_pm   = (const float*)d_in[7];
    const float* E_d    = (const float*)d_in[8];
    const float* E_p    = (const float*)d_in[9];
    const float* E_m    = (const float*)d_in[10];
    const float* W_homo = (const float*)d_in[11];
    const float* Wh_d   = (const float*)d_in[12];
    const float* Wh_p   = (const float*)d_in[13];
    const float* Wh_md  = (const float*)d_in[14];
    const float* Wh_mp  = (const float*)d_in[15];
    const float* rho    = (const float*)d_in[16];
    const float* wih    = (const float*)d_in[17];
    const float* whh    = (const float*)d_in[18];
    const float* bih    = (const float*)d_in[19];
    const float* bhh    = (const float*)d_in[20];
    const float* Wq     = (const float*)d_in[21];
    const float* bq     = (const float*)d_in[22];
    const float* ddi    = (const float*)d_in[23];
    float* out = (float*)d_out;

    k_init<<<3072, 256>>>();
    k0_ew<<<dim3(63,3), 256>>>(E_d, E_p, E_m, W_homo);
    k0_tr<<<640, 256>>>(wih, whh, Wq);
    k1_kernel<<<BV, 256>>>(idx_d, idx_p, idx_m, adj_d, adj_p, adj_m, w_dm, w_pm, E_d, E_p, E_m);
    k2_seq<<<dim3(BV/32, 3), 256>>>(Wh_d, Wh_p, Wh_md, Wh_mp, rho);
    k3_gi<<<dim3(BV/32, 3, 3), 256>>>(bih);
    for (int t = 0; t < 8; t++)
        k4_step<<<dim3(BB/16, 3), 256>>>(bhh, t);
    k5_score<<<BB, 256>>>(bq, out);
    k6_ddi<<<BB, 256>>>(ddi);
    k7_final<<<1, 256>>>(out, out_size);
}

// round 3
// speedup vs baseline: 1.1647x; 1.1647x over previous
#include <cuda_runtime.h>
#include <math.h>

#define BB   1024
#define VV   8
#define ND   32
#define NPR  16
#define NM   24
#define DD   256
#define BV   (BB*VV)
#define VOCD 2000
#define VOCP 1500
#define VOCM 131
#define PAD  260
#define EPSV 1e-8f

// ---------------- static device scratch (no cudaMalloc anywhere) ----------------
__device__ __align__(16) float g_HD[VOCD*DD];
__device__ __align__(16) float g_HP[VOCP*DD];
__device__ __align__(16) float g_HM[VOCM*DD];
__device__ __align__(16) float g_homo0[BV*DD];
__device__ __align__(16) float g_homo1[BV*DD];
__device__ __align__(16) float g_homo2[BV*DD];
__device__ __align__(16) float g_u0[BV*DD];
__device__ __align__(16) float g_u1[BV*DD];
__device__ __align__(16) float g_u2[BV*DD];
__device__ __align__(16) float g_u3[BV*DD];
__device__ __align__(16) float g_seq0[BV*DD];
__device__ __align__(16) float g_seq1[BV*DD];
__device__ __align__(16) float g_seq2[BV*DD];
__device__ __align__(16) float g_gi[3ull*BV*768];
__device__ __align__(16) float g_wihT[3*256*768];
__device__ __align__(16) float g_whhT[3*256*768];
__device__ __align__(16) float g_h[3*BB*DD];
__device__ __align__(16) float g_Wq2T[768*VOCM];
__device__ __align__(16) float g_p[BB*VOCM];
__device__ float g_bpart[BB];

// ---------------- K0a: H = E @ W_homo[set] ----------------
__global__ void __launch_bounds__(256) k0_ew(const float* __restrict__ Ed,
                                             const float* __restrict__ Ep,
                                             const float* __restrict__ Em,
                                             const float* __restrict__ Wh)
{
    __shared__ __align__(16) float se[32*256];
    int set = blockIdx.y;
    int rows = (set==0) ? VOCD : (set==1) ? VOCP : VOCM;
    int r0 = blockIdx.x * 32;
    if (r0 >= rows) return;
    const float* E = (set==0) ? Ed : (set==1) ? Ep : Em;
    float* O       = (set==0) ? g_HD : (set==1) ? g_HP : g_HM;
    const float* W = Wh + (size_t)set*DD*DD;
    int tid = threadIdx.x;

    for (int i = tid; i < 32*64; i += 256) {
        int r = i >> 6, c = i & 63;
        float4 v = (r0 + r < rows) ? __ldg((const float4*)(E + (size_t)(r0+r)*DD) + c)
                                   : make_float4(0.f,0.f,0.f,0.f);
        ((float4*)se)[r*64 + c] = v;
    }
    __syncthreads();

    float acc[32];
    #pragma unroll
    for (int r = 0; r < 32; r++) acc[r] = 0.f;
    for (int k = 0; k < DD; k += 4) {
        float w0 = __ldg(W + (size_t)k*DD + tid);
        float w1 = __ldg(W + (size_t)(k+1)*DD + tid);
        float w2 = __ldg(W + (size_t)(k+2)*DD + tid);
        float w3 = __ldg(W + (size_t)(k+3)*DD + tid);
        #pragma unroll
        for (int r = 0; r < 32; r++) {
            float4 x = *(const float4*)(se + r*256 + k);
            acc[r] = fmaf(x.x,w0,fmaf(x.y,w1,fmaf(x.z,w2,fmaf(x.w,w3,acc[r]))));
        }
    }
    for (int r = 0; r < 32; r++)
        if (r0 + r < rows) O[(size_t)(r0+r)*DD + tid] = acc[r];
}

// ---------------- K0b: transposes + folded Wq ----------------
__global__ void k0_tr(const float* __restrict__ wih,
                      const float* __restrict__ whh,
                      const float* __restrict__ Wq)
{
    const int N1 = 3*768*256;
    const int TOT = 2*N1 + 768*VOCM;
    for (int i = blockIdx.x*blockDim.x + threadIdx.x; i < TOT; i += gridDim.x*blockDim.x) {
        if (i < N1) {
            int g = i/(768*256); int rem = i - g*768*256;
            int r = rem/256; int k = rem - r*256;
            g_wihT[g*768*256 + k*768 + r] = wih[i];
        } else if (i < 2*N1) {
            int j = i - N1;
            int g = j/(768*256); int rem = j - g*768*256;
            int r = rem/256; int k = rem - r*256;
            g_whhT[g*768*256 + k*768 + r] = whh[j];
        } else {
            int o = i - 2*N1;
            int k = o / VOCM, j = o - k*VOCM;
            g_Wq2T[o] = Wq[(size_t)j*1536 + k] + Wq[(size_t)j*1536 + 768 + k];
        }
    }
}

// ---------------- attention helper (register-tiled score GEMM) ----------------
// buf: 2048-float scratch (score partials, then attn matrix with stride 33)
// returns (colsum(softmax(masked h h^T / 16)) . h)[tid]
template<int N>
__device__ __forceinline__ float attn_out(const float* __restrict__ adj,
                                          const float* sh, float* buf, float* scs, int tid)
{
    constexpr int T4    = N/4;
    constexpr int TILES = T4*T4;
    constexpr int QMAX  = (N*N + 255)/256;

    // ---- phase 1: 4x4-tiled score partials, 2 k-groups of 128 ----
    {
        int kg = tid >> 6;           // groups of 64 threads; kg 0..3 but only 0,1 active
        int t  = tid & 63;
        if (kg < 2 && t < TILES) {
            int tr = t / T4, tc = t % T4;
            const float4* base = (const float4*)sh;   // row stride = 65 float4
            float acc[16];
            #pragma unroll
            for (int s = 0; s < 16; s++) acc[s] = 0.f;
            #pragma unroll 4
            for (int kk = 0; kk < 32; kk++) {
                int k4 = kg*32 + kk;
                float4 a[4], b[4];
                #pragma unroll
                for (int i = 0; i < 4; i++) a[i] = base[(tr + i*T4)*65 + k4];
                #pragma unroll
                for (int j = 0; j < 4; j++) b[j] = base[(tc + j*T4)*65 + k4];
                #pragma unroll
                for (int i = 0; i < 4; i++)
                    #pragma unroll
                    for (int j = 0; j < 4; j++)
                        acc[i*4+j] += a[i].x*b[j].x + a[i].y*b[j].y
                                    + a[i].z*b[j].z + a[i].w*b[j].w;
            }
            float* dst = buf + (size_t)kg*TILES*16 + t*16;
            #pragma unroll
            for (int s = 0; s < 16; s++) dst[s] = acc[s];
        }
    }
    __syncthreads();

    // ---- phase 2: combine k-groups + mask (to regs), then rewrite buf as ss ----
    float val[QMAX];
    {
        int cnt = 0;
        for (int q = tid; q < N*N; q += 256, cnt++) {
            int n = q / N, m = q - n*N;
            int i = n / T4, tr = n % T4;
            int j = m / T4, tc = m % T4;
            int idx = (tr*T4 + tc)*16 + i*4 + j;
            float sum = buf[idx] + buf[TILES*16 + idx];
            float av  = __ldg(adj + q);
            val[cnt] = ((av > 0.5f) || (n == m)) ? sum * 0.0625f : -1e9f;
        }
    }
    __syncthreads();
    {
        int cnt = 0;
        for (int q = tid; q < N*N; q += 256, cnt++) {
            int n = q / N, m = q - n*N;
            buf[n*33 + m] = val[cnt];
        }
    }
    __syncthreads();

    // ---- phase 3: row softmax ----
    int lane = tid & 31;
    for (int n = tid >> 5; n < N; n += 8) {
        float v = (lane < N) ? buf[n*33 + lane] : -3.0e38f;
        float mx = v;
        #pragma unroll
        for (int o = 16; o > 0; o >>= 1) mx = fmaxf(mx, __shfl_xor_sync(0xffffffffu, mx, o));
        float e = (lane < N) ? __expf(v - mx) : 0.f;
        float s = e;
        #pragma unroll
        for (int o = 16; o > 0; o >>= 1) s += __shfl_xor_sync(0xffffffffu, s, o);
        if (lane < N) buf[n*33 + lane] = e / s;
    }
    __syncthreads();

    // ---- phase 4: column sums, then weighted aggregation ----
    if (tid < N) {
        float c = 0.f;
        #pragma unroll
        for (int n = 0; n < N; n++) c += buf[n*33 + tid];
        scs[tid] = c;
    }
    __syncthreads();
    float o = 0.f;
    #pragma unroll
    for (int m = 0; m < N; m++) o = fmaf(scs[m], sh[m*PAD + tid], o);
    return o;
}

// ---------------- K1: per-(b,v) fused homo sums + hetero u vectors ----------------
__global__ void __launch_bounds__(256) k1_kernel(
    const int* __restrict__ idx_d, const int* __restrict__ idx_p, const int* __restrict__ idx_m,
    const float* __restrict__ adj_d, const float* __restrict__ adj_p, const float* __restrict__ adj_m,
    const float* __restrict__ wdm_g, const float* __restrict__ wpm_g,
    const float* __restrict__ E_d, const float* __restrict__ E_p, const float* __restrict__ E_m)
{
    __shared__ __align__(16) float sh[32*PAD];
    __shared__ __align__(16) float buf[2048];   // aliased: w-matrix / score partials / attn
    __shared__ float scdm[NM], scpm[NM], scmd[ND], scmp[NPR];
    __shared__ float srow[ND], scol[NM], scs[32];
    __shared__ int sidx[ND];

    int bid = blockIdx.x;
    int v = bid & 7;
    int tid = threadIdx.x;
    size_t off = (size_t)bid*DD + tid;
    float* sw = buf;    // 768 floats, used only before attn_out<NM>

    float u_d = 0.f, u_p = 0.f, sm_out = 0.f;
    if (v > 0) {
        const float* wdm = wdm_g + (size_t)bid*ND*NM;
        for (int i = tid; i < ND*NM; i += 256) sw[i] = wdm[i];
        if (tid < NM) sidx[tid] = __ldg(idx_m + (size_t)(bid-1)*NM + tid);
        __syncthreads();
        for (int i = tid; i < NM*64; i += 256) {
            int r = i >> 6, c = i & 63;
            ((float4*)(sh + r*PAD))[c] = __ldg((const float4*)(g_HM + (size_t)sidx[r]*DD) + c);
        }
        if (tid < ND) { float s = 0.f; for (int m=0;m<NM;m++) s += sw[tid*NM+m]; srow[tid] = s + EPSV; }
        __syncthreads();
        if (tid < NM) {
            float c = 0.f, cs = 0.f;
            for (int n=0;n<ND;n++) { float w = sw[n*NM+tid]; c += w/srow[n]; cs += w; }
            scdm[tid] = c; scol[tid] = cs + EPSV;
        }
        __syncthreads();
        if (tid < ND) { float c = 0.f; for (int m=0;m<NM;m++) c += sw[tid*NM+m]/scol[m]; scmd[tid] = c; }
        __syncthreads();
        const float* wpm = wpm_g + (size_t)bid*NPR*NM;
        for (int i = tid; i < NPR*NM; i += 256) sw[i] = wpm[i];
        __syncthreads();
        if (tid < NPR) { float s = 0.f; for (int m=0;m<NM;m++) s += sw[tid*NM+m]; srow[tid] = s + EPSV; }
        __syncthreads();
        if (tid < NM) {
            float c = 0.f, cs = 0.f;
            for (int n=0;n<NPR;n++) { float w = sw[n*NM+tid]; c += w/srow[n]; cs += w; }
            scpm[tid] = c; scol[tid] = cs + EPSV;
        }
        __syncthreads();
        if (tid < NPR) { float c = 0.f; for (int m=0;m<NM;m++) c += sw[tid*NM+m]/scol[m]; scmp[tid] = c; }
        __syncthreads();
        #pragma unroll 4
        for (int m = 0; m < NM; m++) {
            float e = __ldg(E_m + (size_t)sidx[m]*DD + tid);
            u_d = fmaf(scdm[m], e, u_d);
            u_p = fmaf(scpm[m], e, u_p);
        }
        sm_out = attn_out<NM>(adj_m + (size_t)bid*NM*NM, sh, buf, scs, tid);
    }
    g_homo2[off] = sm_out; g_u0[off] = u_d; g_u1[off] = u_p;
    __syncthreads();

    // ---- diag ----
    if (tid < ND) sidx[tid] = __ldg(idx_d + (size_t)bid*ND + tid);
    __syncthreads();
    for (int i = tid; i < ND*64; i += 256) {
        int r = i >> 6, c = i & 63;
        ((float4*)(sh + r*PAD))[c] = __ldg((const float4*)(g_HD + (size_t)sidx[r]*DD) + c);
    }
    __syncthreads();
    float sd_out = attn_out<ND>(adj_d + (size_t)bid*ND*ND, sh, buf, scs, tid);
    float u_md = 0.f;
    if (v > 0) {
        #pragma unroll 4
        for (int n = 0; n < ND; n++)
            u_md = fmaf(scmd[n], __ldg(E_d + (size_t)sidx[n]*DD + tid), u_md);
    }
    g_homo0[off] = sd_out; g_u2[off] = u_md;
    __syncthreads();

    // ---- proc ----
    if (tid < NPR) sidx[tid] = __ldg(idx_p + (size_t)bid*NPR + tid);
    __syncthreads();
    for (int i = tid; i < NPR*64; i += 256) {
        int r = i >> 6, c = i & 63;
        ((float4*)(sh + r*PAD))[c] = __ldg((const float4*)(g_HP + (size_t)sidx[r]*DD) + c);
    }
    __syncthreads();
    float sp_out = attn_out<NPR>(adj_p + (size_t)bid*NPR*NPR, sh, buf, scs, tid);
    float u_mp = 0.f;
    if (v > 0) {
        #pragma unroll 4
        for (int n = 0; n < NPR; n++)
            u_mp = fmaf(scmp[n], __ldg(E_p + (size_t)sidx[n]*DD + tid), u_mp);
    }
    g_homo1[off] = sp_out; g_u3[off] = u_mp;
}

// ---------------- K2: seq = rho0*homo + rho1*(u @ Wh) ----------------
__global__ void __launch_bounds__(256) k2_seq(const float* __restrict__ Wh_d,
                                              const float* __restrict__ Wh_p,
                                              const float* __restrict__ Wh_md,
                                              const float* __restrict__ Wh_mp,
                                              const float* __restrict__ rho)
{
    __shared__ __align__(16) float su[32*256];
    int set = blockIdx.y;
    int r0 = blockIdx.x * 32;
    int tid = threadIdx.x;
    const float* U1 = (set==0) ? g_u0 : (set==1) ? g_u1 : g_u2;
    const float* W1 = (set==0) ? Wh_d : (set==1) ? Wh_p : Wh_md;

    float acc[32];
    #pragma unroll
    for (int r = 0; r < 32; r++) acc[r] = 0.f;
    for (int i = tid; i < 32*256; i += 256) su[i] = U1[(size_t)r0*256 + i];
    __syncthreads();
    for (int k = 0; k < 256; k += 4) {
        float w0 = __ldg(W1 + (size_t)k*256 + tid);
        float w1 = __ldg(W1 + (size_t)(k+1)*256 + tid);
        float w2 = __ldg(W1 + (size_t)(k+2)*256 + tid);
        float w3 = __ldg(W1 + (size_t)(k+3)*256 + tid);
        #pragma unroll
        for (int r = 0; r < 32; r++) {
            float4 x = *(const float4*)(su + r*256 + k);
            acc[r] = fmaf(x.x,w0,fmaf(x.y,w1,fmaf(x.z,w2,fmaf(x.w,w3,acc[r]))));
        }
    }
    if (set == 2) {
        __syncthreads();
        for (int i = tid; i < 32*256; i += 256) su[i] = g_u3[(size_t)r0*256 + i];
        __syncthreads();
        for (int k = 0; k < 256; k += 4) {
            float w0 = __ldg(Wh_mp + (size_t)k*256 + tid);
            float w1 = __ldg(Wh_mp + (size_t)(k+1)*256 + tid);
            float w2 = __ldg(Wh_mp + (size_t)(k+2)*256 + tid);
            float w3 = __ldg(Wh_mp + (size_t)(k+3)*256 + tid);
            #pragma unroll
            for (int r = 0; r < 32; r++) {
                float4 x = *(const float4*)(su + r*256 + k);
                acc[r] = fmaf(x.x,w0,fmaf(x.y,w1,fmaf(x.z,w2,fmaf(x.w,w3,acc[r]))));
            }
        }
    }
    float rh0 = __ldg(rho + set*2), rh1 = __ldg(rho + set*2 + 1);
    const float* H = (set==0) ? g_homo0 : (set==1) ? g_homo1 : g_homo2;
    float* S       = (set==0) ? g_seq0 : (set==1) ? g_seq1 : g_seq2;
    for (int r = 0; r < 32; r++) {
        size_t o = (size_t)(r0+r)*256 + tid;
        S[o] = rh0 * H[o] + rh1 * acc[r];
    }
}

// ---------------- K3: gi = seq @ wihT + bih ----------------
__global__ void __launch_bounds__(256) k3_gi(const float* __restrict__ bih)
{
    __shared__ __align__(16) float su[32*256];
    int g = blockIdx.z;
    int j = blockIdx.y*256 + threadIdx.x;
    int r0 = blockIdx.x * 32;
    int tid = threadIdx.x;
    const float* S = (g==0) ? g_seq0 : (g==1) ? g_seq1 : g_seq2;
    const float* W = g_wihT + (size_t)g*256*768;

    for (int i = tid; i < 32*256; i += 256) su[i] = S[(size_t)r0*256 + i];
    __syncthreads();
    float acc[32];
    #pragma unroll
    for (int r = 0; r < 32; r++) acc[r] = 0.f;
    for (int k = 0; k < 256; k += 4) {
        float w0 = __ldg(W + (size_t)k*768 + j);
        float w1 = __ldg(W + (size_t)(k+1)*768 + j);
        float w2 = __ldg(W + (size_t)(k+2)*768 + j);
        float w3 = __ldg(W + (size_t)(k+3)*768 + j);
        #pragma unroll
        for (int r = 0; r < 32; r++) {
            float4 x = *(const float4*)(su + r*256 + k);
            acc[r] = fmaf(x.x,w0,fmaf(x.y,w1,fmaf(x.z,w2,fmaf(x.w,w3,acc[r]))));
        }
    }
    float bias = __ldg(bih + g*768 + j);
    for (int r = 0; r < 32; r++)
        g_gi[((size_t)g*BV + r0 + r)*768 + j] = acc[r] + bias;
}

// ---------------- K4a: GRU time step 0 (h=0 -> closed form, no GEMM) ----------------
__global__ void __launch_bounds__(256) k4_step0(const float* __restrict__ bhh)
{
    int idx = blockIdx.x*blockDim.x + threadIdx.x;   // over 3*BB*256
    if (idx >= 3*BB*DD) return;
    int g   = idx / (BB*DD);
    int rem = idx - g*BB*DD;
    int b   = rem >> 8;
    int col = rem & 255;
    size_t gio = ((size_t)g*BV + (size_t)b*VV + 0)*768;
    float ir  = g_gi[gio + col];
    float iz  = g_gi[gio + 256 + col];
    float in_ = g_gi[gio + 512 + col];
    float br = __ldg(bhh + g*768 + col);
    float bz = __ldg(bhh + g*768 + 256 + col);
    float bn = __ldg(bhh + g*768 + 512 + col);
    float rr = 1.f/(1.f+__expf(-(ir + br)));
    float zz = 1.f/(1.f+__expf(-(iz + bz)));
    float nn = tanhf(in_ + rr*bn);
    g_h[idx] = (1.f - zz)*nn;
}

// ---------------- K4: one GRU time step ----------------
__global__ void __launch_bounds__(256) k4_step(const float* __restrict__ bhh, int t)
{
    __shared__ __align__(16) float sh16[16*256];
    int g = blockIdx.y;
    int r0 = blockIdx.x * 16;
    int tid = threadIdx.x;
    const float* W = g_whhT + (size_t)g*256*768;
    float* H = g_h + (size_t)g*BB*DD;

    for (int i = tid; i < 16*64; i += 256) {
        int r = i >> 6, c = i & 63;
        ((float4*)(sh16 + r*256))[c] = *(const float4*)(H + (size_t)(r0+r)*256 + c*4);
    }
    __syncthreads();
    float ar[16], az[16], an[16];
    #pragma unroll
    for (int r = 0; r < 16; r++) { ar[r]=0.f; az[r]=0.f; an[r]=0.f; }
    for (int k = 0; k < 256; k += 4) {
        float4 wr, wz, wn;
        wr.x=__ldg(W+(size_t)k*768+tid);           wr.y=__ldg(W+(size_t)(k+1)*768+tid);
        wr.z=__ldg(W+(size_t)(k+2)*768+tid);       wr.w=__ldg(W+(size_t)(k+3)*768+tid);
        wz.x=__ldg(W+(size_t)k*768+256+tid);       wz.y=__ldg(W+(size_t)(k+1)*768+256+tid);
        wz.z=__ldg(W+(size_t)(k+2)*768+256+tid);   wz.w=__ldg(W+(size_t)(k+3)*768+256+tid);
        wn.x=__ldg(W+(size_t)k*768+512+tid);       wn.y=__ldg(W+(size_t)(k+1)*768+512+tid);
        wn.z=__ldg(W+(size_t)(k+2)*768+512+tid);   wn.w=__ldg(W+(size_t)(k+3)*768+512+tid);
        #pragma unroll
        for (int r = 0; r < 16; r++) {
            float4 x = *(const float4*)(sh16 + r*256 + k);
            ar[r]=fmaf(x.x,wr.x,fmaf(x.y,wr.y,fmaf(x.z,wr.z,fmaf(x.w,wr.w,ar[r]))));
            az[r]=fmaf(x.x,wz.x,fmaf(x.y,wz.y,fmaf(x.z,wz.z,fmaf(x.w,wz.w,az[r]))));
            an[r]=fmaf(x.x,wn.x,fmaf(x.y,wn.y,fmaf(x.z,wn.z,fmaf(x.w,wn.w,an[r]))));
        }
    }
    float br = __ldg(bhh + g*768 + tid);
    float bz = __ldg(bhh + g*768 + 256 + tid);
    float bn = __ldg(bhh + g*768 + 512 + tid);
    for (int r = 0; r < 16; r++) {
        size_t gio = ((size_t)g*BV + (size_t)(r0+r)*VV + t)*768;
        float ir  = g_gi[gio + tid];
        float iz  = g_gi[gio + 256 + tid];
        float in_ = g_gi[gio + 512 + tid];
        float rr = 1.f/(1.f+__expf(-(ir + ar[r] + br)));
        float zz = 1.f/(1.f+__expf(-(iz + az[r] + bz)));
        float nn = tanhf(in_ + rr*(an[r] + bn));
        float hold = sh16[r*256 + tid];
        H[(size_t)(r0+r)*256 + tid] = (1.f - zz)*nn + zz*hold;
    }
}

// ---------------- K5: score + sigmoid ----------------
__global__ void __launch_bounds__(256) k5_score(const float* __restrict__ bq, float* __restrict__ out)
{
    __shared__ float shc[768];
    int b = blockIdx.x, tid = threadIdx.x;
    for (int i = tid; i < 768; i += 256) {
        int g = i >> 8, k = i & 255;
        float h = g_h[(size_t)g*BB*DD + (size_t)b*DD + k];
        shc[i] = fmaxf(h, 0.f);
    }
    __syncthreads();
    if (tid < VOCM) {
        float acc = 0.f;
        for (int k = 0; k < 768; k++) acc = fmaf(shc[k], __ldg(g_Wq2T + k*VOCM + tid), acc);
        float sc = acc + __ldg(bq + tid);
        out[(size_t)b*VOCM + tid] = sc;
        g_p[(size_t)b*VOCM + tid] = 1.f/(1.f+__expf(-sc));
    }
}

// ---------------- K6: per-b ddi partial ----------------
__global__ void __launch_bounds__(256) k6_ddi(const float* __restrict__ ddi)
{
    __shared__ float sp[VOCM];
    __shared__ float red[8];
    int b = blockIdx.x, tid = threadIdx.x;
    for (int i = tid; i < VOCM; i += 256) sp[i] = g_p[(size_t)b*VOCM + i];
    __syncthreads();
    float val = 0.f;
    if (tid < VOCM) {
        float q = 0.f;
        for (int i = 0; i < VOCM; i++) q = fmaf(sp[i], __ldg(ddi + (size_t)i*VOCM + tid), q);
        val = sp[tid]*q;
    }
    for (int o = 16; o > 0; o >>= 1) val += __shfl_xor_sync(0xffffffffu, val, o);
    if ((tid & 31) == 0) red[tid >> 5] = val;
    __syncthreads();
    if (tid == 0) {
        float s = 0.f;
        for (int w = 0; w < 8; w++) s += red[w];
        g_bpart[b] = s;
    }
}

// ---------------- K7: deterministic final reduction ----------------
__global__ void k7_final(float* __restrict__ out, int out_size)
{
    __shared__ float red[8];
    int tid = threadIdx.x;
    float s = 0.f;
    for (int i = tid; i < BB; i += 256) s += g_bpart[i];
    for (int o = 16; o > 0; o >>= 1) s += __shfl_xor_sync(0xffffffffu, s, o);
    if ((tid & 31) == 0) red[tid >> 5] = s;
    __syncthreads();
    if (tid == 0) {
        float t = 0.f;
        for (int w = 0; w < 8; w++) t += red[w];
        if (out_size > BB*VOCM) out[BB*VOCM] = 0.0005f * t;
    }
}

// ---------------- launch ----------------
extern "C" void kernel_launch(void* const* d_in, const int* in_sizes, int n_in,
                              void* d_out, int out_size)
{
    const int*   idx_d  = (const int*)d_in[0];
    const int*   idx_p  = (const int*)d_in[1];
    const int*   idx_m  = (const int*)d_in[2];
    const float* adj_d  = (const float*)d_in[3];
    const float* adj_p  = (const float*)d_in[4];
    const float* adj_m  = (const float*)d_in[5];
    const float* w_dm   = (const float*)d_in[6];
    const float* w_pm   = (const float*)d_in[7];
    const float* E_d    = (const float*)d_in[8];
    const float* E_p    = (const float*)d_in[9];
    const float* E_m    = (const float*)d_in[10];
    const float* W_homo = (const float*)d_in[11];
    const float* Wh_d   = (const float*)d_in[12];
    const float* Wh_p   = (const float*)d_in[13];
    const float* Wh_md  = (const float*)d_in[14];
    const float* Wh_mp  = (const float*)d_in[15];
    const float* rho    = (const float*)d_in[16];
    const float* wih    = (const float*)d_in[17];
    const float* whh    = (const float*)d_in[18];
    const float* bih    = (const float*)d_in[19];
    const float* bhh    = (const float*)d_in[20];
    const float* Wq     = (const float*)d_in[21];
    const float* bq     = (const float*)d_in[22];
    const float* ddi    = (const float*)d_in[23];
    float* out = (float*)d_out;

    k0_ew<<<dim3(63,3), 256>>>(E_d, E_p, E_m, W_homo);
    k0_tr<<<640, 256>>>(wih, whh, Wq);
    k1_kernel<<<BV, 256>>>(idx_d, idx_p, idx_m, adj_d, adj_p, adj_m, w_dm, w_pm, E_d, E_p, E_m);
    k2_seq<<<dim3(BV/32, 3), 256>>>(Wh_d, Wh_p, Wh_md, Wh_mp, rho);
    k3_gi<<<dim3(BV/32, 3, 3), 256>>>(bih);
    k4_step0<<<3*BB*DD/256, 256>>>(bhh);
    for (int t = 1; t < 8; t++)
        k4_step<<<dim3(BB/16, 3), 256>>>(bhh, t);
    k5_score<<<BB, 256>>>(bq, out);
    k6_ddi<<<BB, 256>>>(ddi);
    k7_final<<<1, 256>>>(out, out_size);
}